// round 3
// baseline (speedup 1.0000x reference)
#include <cuda_runtime.h>
#include <cstddef>

// Problem constants
#define BATCH   2048
#define NTOK    98
#define EMB     192
#define NHEADS  6
#define HDIM    32
#define NWIN    64
#define NN      (NTOK*NTOK)        // 9604
#define MROWS   (BATCH*NTOK)       // 200704

// Scratch (device globals — no allocation allowed)
__device__ float d_qkv[(size_t)BATCH * 3 * NHEADS * NTOK * HDIM];   // [b][which][h][n][d]  ~462MB
__device__ float d_attnout[(size_t)BATCH * NTOK * EMB];             // [b][n][h*32+d]       ~154MB
__device__ float d_bias[NHEADS * NN];                               // [h][i][j]

// ---------------------------------------------------------------------------
// Kernel 1: gather relative-position bias  bias[h][i][j] = table[rel[i,j]*6+h]
// ---------------------------------------------------------------------------
__global__ void gather_bias_kernel(const float* __restrict__ table,
                                   const int* __restrict__ rel) {
    int idx = blockIdx.x * blockDim.x + threadIdx.x;
    if (idx < NN) {
        int r = rel[idx];
        #pragma unroll
        for (int h = 0; h < NHEADS; h++)
            d_bias[h * NN + idx] = table[r * NHEADS + h];
    }
}

// ---------------------------------------------------------------------------
// Kernel 2: QKV GEMM.  C[m, c] = x[m,:] . qkv_w[c,:] + qkv_b[c]
// M = 200704, K = 192, Ncols = 576. Tile 128x64x16, 256 threads, 8x4 micro.
// Epilogue permutes into d_qkv[b][which][h][n][d].
// ---------------------------------------------------------------------------
__global__ __launch_bounds__(256) void gemm_qkv_kernel(
    const float* __restrict__ A, const float* __restrict__ W,
    const float* __restrict__ bias) {
    __shared__ float As[16][128];
    __shared__ float Bs[16][64];

    const int tid = threadIdx.x;
    const int tx = tid & 15;        // n-dir 0..15
    const int ty = tid >> 4;        // m-dir 0..15
    const int m0 = blockIdx.y * 128;
    const int n0 = blockIdx.x * 64;

    // load lanes
    const int lm  = tid & 127;            // A row
    const int lkh = (tid >> 7) * 8;       // A k-offset (0 or 8)
    const int ln  = tid & 63;             // B row
    const int lkq = (tid >> 6) * 4;       // B k-offset (0,4,8,12)

    float acc[8][4];
    #pragma unroll
    for (int i = 0; i < 8; i++)
        #pragma unroll
        for (int j = 0; j < 4; j++) acc[i][j] = 0.f;

    const float* ap = A + (size_t)(m0 + lm) * EMB + lkh;
    const float* bp = W + (size_t)(n0 + ln) * EMB + lkq;

    for (int kt = 0; kt < EMB; kt += 16) {
        float4 a0 = *(const float4*)(ap + kt);
        float4 a1 = *(const float4*)(ap + kt + 4);
        float4 b0 = *(const float4*)(bp + kt);
        As[lkh+0][lm] = a0.x; As[lkh+1][lm] = a0.y;
        As[lkh+2][lm] = a0.z; As[lkh+3][lm] = a0.w;
        As[lkh+4][lm] = a1.x; As[lkh+5][lm] = a1.y;
        As[lkh+6][lm] = a1.z; As[lkh+7][lm] = a1.w;
        Bs[lkq+0][ln] = b0.x; Bs[lkq+1][ln] = b0.y;
        Bs[lkq+2][ln] = b0.z; Bs[lkq+3][ln] = b0.w;
        __syncthreads();
        #pragma unroll
        for (int k = 0; k < 16; k++) {
            float4 ta0 = *(const float4*)&As[k][ty * 8];
            float4 ta1 = *(const float4*)&As[k][ty * 8 + 4];
            float4 tb  = *(const float4*)&Bs[k][tx * 4];
            float a[8] = {ta0.x, ta0.y, ta0.z, ta0.w, ta1.x, ta1.y, ta1.z, ta1.w};
            float b[4] = {tb.x, tb.y, tb.z, tb.w};
            #pragma unroll
            for (int i = 0; i < 8; i++)
                #pragma unroll
                for (int j = 0; j < 4; j++)
                    acc[i][j] = fmaf(a[i], b[j], acc[i][j]);
        }
        __syncthreads();
    }

    #pragma unroll
    for (int i = 0; i < 8; i++) {
        int mg = m0 + ty * 8 + i;
        int bb = mg / NTOK;
        int nn = mg - bb * NTOK;
        #pragma unroll
        for (int j = 0; j < 4; j++) {
            int c = n0 + tx * 4 + j;
            int which = c / EMB;
            int rem = c - which * EMB;
            int h = rem >> 5;
            int d = rem & 31;
            size_t dst = ((((size_t)bb * 3 + which) * NHEADS + h) * NTOK + nn) * HDIM + d;
            d_qkv[dst] = acc[i][j] + bias[c];
        }
    }
}

// ---------------------------------------------------------------------------
// Kernel 3: fused attention per (b, h). Scores+softmax held in registers.
// ---------------------------------------------------------------------------
#define SPAD 36  // padded row stride for q/k/v tiles (float4-aligned, conflict-safe where it matters)

__global__ __launch_bounds__(128) void attn_kernel(const float* __restrict__ mask) {
    __shared__ __align__(16) float sh[3 * NTOK * SPAD];
    float* qs = sh;
    float* ks = sh + NTOK * SPAD;
    float* vs = sh + 2 * NTOK * SPAD;

    const int bh = blockIdx.x;
    const int b = bh / NHEADS;
    const int h = bh - b * NHEADS;
    const int w = b & (NWIN - 1);

    const size_t base = (((size_t)b * 3) * NHEADS + h) * (NTOK * HDIM);
    const float* qg = d_qkv + base;                            // which = 0
    const float* kg = qg + (size_t)NHEADS * NTOK * HDIM;       // which = 1
    const float* vg = qg + 2 * (size_t)NHEADS * NTOK * HDIM;   // which = 2

    for (int idx = threadIdx.x; idx < NTOK * HDIM; idx += 128) {
        int n = idx >> 5, d = idx & 31;
        qs[n * SPAD + d] = qg[idx];
        ks[n * SPAD + d] = kg[idx];
        vs[n * SPAD + d] = vg[idx];
    }
    __syncthreads();

    const int i = threadIdx.x;
    if (i < NTOK) {
        float qr[HDIM];
        #pragma unroll
        for (int d = 0; d < HDIM; d++) qr[d] = qs[i * SPAD + d];

        const float* brow = d_bias + (h * NN + i * NTOK);
        const float* mrow = mask + ((size_t)w * NN + i * NTOK);
        const float scale = 0.17677669529663687f;  // 32^-0.5

        float s[NTOK];
        float mx = -1e30f;
        #pragma unroll
        for (int j = 0; j < NTOK; j++) {
            float acc = 0.f;
            #pragma unroll
            for (int d4 = 0; d4 < 8; d4++) {
                float4 kv = *(const float4*)&ks[j * SPAD + d4 * 4];
                acc = fmaf(qr[d4*4+0], kv.x, acc);
                acc = fmaf(qr[d4*4+1], kv.y, acc);
                acc = fmaf(qr[d4*4+2], kv.z, acc);
                acc = fmaf(qr[d4*4+3], kv.w, acc);
            }
            float val = fmaf(acc, scale, brow[j] + mrow[j]);
            s[j] = val;
            mx = fmaxf(mx, val);
        }
        float sum = 0.f;
        #pragma unroll
        for (int j = 0; j < NTOK; j++) {
            float e = __expf(s[j] - mx);
            s[j] = e;
            sum += e;
        }
        float inv = 1.f / sum;

        float o[HDIM];
        #pragma unroll
        for (int d = 0; d < HDIM; d++) o[d] = 0.f;
        #pragma unroll
        for (int j = 0; j < NTOK; j++) {
            float p = s[j];
            #pragma unroll
            for (int d4 = 0; d4 < 8; d4++) {
                float4 vv = *(const float4*)&vs[j * SPAD + d4 * 4];
                o[d4*4+0] = fmaf(p, vv.x, o[d4*4+0]);
                o[d4*4+1] = fmaf(p, vv.y, o[d4*4+1]);
                o[d4*4+2] = fmaf(p, vv.z, o[d4*4+2]);
                o[d4*4+3] = fmaf(p, vv.w, o[d4*4+3]);
            }
        }
        float* op = d_attnout + ((size_t)b * NTOK + i) * EMB + h * HDIM;
        #pragma unroll
        for (int d = 0; d < HDIM; d++) op[d] = o[d] * inv;
    }
}

// ---------------------------------------------------------------------------
// Kernel 4: output projection.  out[m,c] = attnout[m,:] . o_w[c,:] + o_b[c]
// Same GEMM structure, Ncols = 192, direct store.
// ---------------------------------------------------------------------------
__global__ __launch_bounds__(256) void gemm_proj_kernel(
    const float* __restrict__ W, const float* __restrict__ bias,
    float* __restrict__ out) {
    __shared__ float As[16][128];
    __shared__ float Bs[16][64];

    const int tid = threadIdx.x;
    const int tx = tid & 15;
    const int ty = tid >> 4;
    const int m0 = blockIdx.y * 128;
    const int n0 = blockIdx.x * 64;

    const int lm  = tid & 127;
    const int lkh = (tid >> 7) * 8;
    const int ln  = tid & 63;
    const int lkq = (tid >> 6) * 4;

    float acc[8][4];
    #pragma unroll
    for (int i = 0; i < 8; i++)
        #pragma unroll
        for (int j = 0; j < 4; j++) acc[i][j] = 0.f;

    const float* ap = d_attnout + (size_t)(m0 + lm) * EMB + lkh;
    const float* bp = W + (size_t)(n0 + ln) * EMB + lkq;

    for (int kt = 0; kt < EMB; kt += 16) {
        float4 a0 = *(const float4*)(ap + kt);
        float4 a1 = *(const float4*)(ap + kt + 4);
        float4 b0 = *(const float4*)(bp + kt);
        As[lkh+0][lm] = a0.x; As[lkh+1][lm] = a0.y;
        As[lkh+2][lm] = a0.z; As[lkh+3][lm] = a0.w;
        As[lkh+4][lm] = a1.x; As[lkh+5][lm] = a1.y;
        As[lkh+6][lm] = a1.z; As[lkh+7][lm] = a1.w;
        Bs[lkq+0][ln] = b0.x; Bs[lkq+1][ln] = b0.y;
        Bs[lkq+2][ln] = b0.z; Bs[lkq+3][ln] = b0.w;
        __syncthreads();
        #pragma unroll
        for (int k = 0; k < 16; k++) {
            float4 ta0 = *(const float4*)&As[k][ty * 8];
            float4 ta1 = *(const float4*)&As[k][ty * 8 + 4];
            float4 tb  = *(const float4*)&Bs[k][tx * 4];
            float a[8] = {ta0.x, ta0.y, ta0.z, ta0.w, ta1.x, ta1.y, ta1.z, ta1.w};
            float b[4] = {tb.x, tb.y, tb.z, tb.w};
            #pragma unroll
            for (int i = 0; i < 8; i++)
                #pragma unroll
                for (int j = 0; j < 4; j++)
                    acc[i][j] = fmaf(a[i], b[j], acc[i][j]);
        }
        __syncthreads();
    }

    #pragma unroll
    for (int i = 0; i < 8; i++) {
        int mg = m0 + ty * 8 + i;
        #pragma unroll
        for (int j = 0; j < 4; j++) {
            int c = n0 + tx * 4 + j;
            out[(size_t)mg * EMB + c] = acc[i][j] + bias[c];
        }
    }
}

// ---------------------------------------------------------------------------
// Launch
// ---------------------------------------------------------------------------
extern "C" void kernel_launch(void* const* d_in, const int* in_sizes, int n_in,
                              void* d_out, int out_size) {
    const float* x          = (const float*)d_in[0];
    const float* mask       = (const float*)d_in[1];
    const float* qkv_w      = (const float*)d_in[2];
    const float* qkv_b      = (const float*)d_in[3];
    const float* o_w        = (const float*)d_in[4];
    const float* o_b        = (const float*)d_in[5];
    const float* bias_table = (const float*)d_in[6];
    const int*   rel_index  = (const int*)d_in[7];
    float* out = (float*)d_out;

    gather_bias_kernel<<<(NN + 127) / 128, 128>>>(bias_table, rel_index);

    // QKV: M = 200704 (1568 tiles of 128), Ncols = 576 (9 tiles of 64)
    gemm_qkv_kernel<<<dim3(9, 1568), 256>>>(x, qkv_w, qkv_b);

    // Attention: one block per (batch, head)
    attn_kernel<<<BATCH * NHEADS, 128>>>(mask);

    // Projection: Ncols = 192 (3 tiles of 64)
    gemm_proj_kernel<<<dim3(3, 1568), 256>>>(o_w, o_b, out);
}

// round 7
// speedup vs baseline: 1.9245x; 1.9245x over previous
#include <cuda_runtime.h>
#include <cstddef>
#include <cstdint>

// Problem constants
#define BATCH   2048
#define NTOK    98
#define EMB     192
#define NHEADS  6
#define HDIM    32
#define NWIN    64
#define NN      (NTOK*NTOK)        // 9604

// Scratch (device globals — no allocation allowed)
__device__ float d_qkv[(size_t)BATCH * 3 * NHEADS * NTOK * HDIM];   // [b][which][h][n][d]
__device__ float d_attnout[(size_t)BATCH * NTOK * EMB];             // [b][n][h*32+d]
__device__ float d_bm[(size_t)NHEADS * NWIN * NN];                  // bias+mask combined [h][w][i][j] 14.7MB

// ---------------------------------------------------------------------------
// helpers
// ---------------------------------------------------------------------------
__device__ __forceinline__ uint32_t f2tf32(float f) {
    uint32_t u;
    asm("cvt.rna.tf32.f32 %0, %1;" : "=r"(u) : "f"(f));
    return u;
}

__device__ __forceinline__ void mma_tf32(float c[4], const uint32_t a[4], const uint32_t b[2]) {
    asm volatile(
        "mma.sync.aligned.m16n8k8.row.col.f32.tf32.tf32.f32 "
        "{%0,%1,%2,%3},{%4,%5,%6,%7},{%8,%9},{%0,%1,%2,%3};"
        : "+f"(c[0]), "+f"(c[1]), "+f"(c[2]), "+f"(c[3])
        : "r"(a[0]), "r"(a[1]), "r"(a[2]), "r"(a[3]), "r"(b[0]), "r"(b[1]));
}

// ---------------------------------------------------------------------------
// Kernel 1: combine bias + mask:  d_bm[h][w][i][j] = table[rel[i,j]*6+h] + mask[w][i][j]
// One block row per (h, w); fully coalesced writes; rel/table stay in L2.
// ---------------------------------------------------------------------------
__global__ void combine_bias_kernel(const float* __restrict__ table,
                                    const int* __restrict__ rel,
                                    const float* __restrict__ mask) {
    const int h = blockIdx.y;
    const int w = blockIdx.z;
    const float* mrow = mask + (size_t)w * NN;
    float* dst = d_bm + ((size_t)(h * NWIN + w)) * NN;
    for (int idx = blockIdx.x * blockDim.x + threadIdx.x; idx < NN;
         idx += gridDim.x * blockDim.x) {
        dst[idx] = table[rel[idx] * NHEADS + h] + mrow[idx];
    }
}

// ---------------------------------------------------------------------------
// tf32 tensor-core GEMM: C[m, c] = A[m,:] . W[c,:] + bias[c]
// Tile 128x64x32, 256 threads (8 warps: 4 m-warps x 2 n-warps, 32x32 each).
// Per warp: 2 m16 tiles x 4 n8 tiles of m16n8k8 mma.
// ---------------------------------------------------------------------------
#define SA 136   // As row stride (136 % 32 == 8 -> conflict-free frag loads)
#define SB 72    // Bs row stride

// QKV variant: epilogue permutes into d_qkv[b][which][h][n][d]
__global__ __launch_bounds__(256) void gemm_qkv_kernel(
    const float* __restrict__ A, const float* __restrict__ W,
    const float* __restrict__ bias) {
    __shared__ uint32_t As[32 * SA];
    __shared__ uint32_t Bs[32 * SB];

    const int tid = threadIdx.x;
    const int lane = tid & 31;
    const int wid = tid >> 5;
    const int wm = wid >> 1;       // 0..3
    const int wn = wid & 1;        // 0..1
    const int m0 = blockIdx.y * 128;
    const int n0 = blockIdx.x * 64;

    const int lm  = tid & 127;
    const int lka = (tid >> 7) * 16;
    const int ln  = tid & 63;
    const int lkb = (tid >> 6) * 8;

    float acc[2][4][4];
    #pragma unroll
    for (int mt = 0; mt < 2; mt++)
        #pragma unroll
        for (int nt = 0; nt < 4; nt++)
            #pragma unroll
            for (int r = 0; r < 4; r++) acc[mt][nt][r] = 0.f;

    const float* ap = A + (size_t)(m0 + lm) * EMB + lka;
    const float* bp = W + (size_t)(n0 + ln) * EMB + lkb;

    for (int kt = 0; kt < EMB; kt += 32) {
        #pragma unroll
        for (int q = 0; q < 4; q++) {
            float4 v = *(const float4*)(ap + kt + q * 4);
            int k = lka + q * 4;
            As[(k + 0) * SA + lm] = f2tf32(v.x);
            As[(k + 1) * SA + lm] = f2tf32(v.y);
            As[(k + 2) * SA + lm] = f2tf32(v.z);
            As[(k + 3) * SA + lm] = f2tf32(v.w);
        }
        #pragma unroll
        for (int q = 0; q < 2; q++) {
            float4 v = *(const float4*)(bp + kt + q * 4);
            int k = lkb + q * 4;
            Bs[(k + 0) * SB + ln] = f2tf32(v.x);
            Bs[(k + 1) * SB + ln] = f2tf32(v.y);
            Bs[(k + 2) * SB + ln] = f2tf32(v.z);
            Bs[(k + 3) * SB + ln] = f2tf32(v.w);
        }
        __syncthreads();
        #pragma unroll
        for (int ks = 0; ks < 32; ks += 8) {
            const int ka = ks + (lane & 3);
            const int ra = wm * 32 + (lane >> 2);
            uint32_t af[2][4];
            #pragma unroll
            for (int mt = 0; mt < 2; mt++) {
                af[mt][0] = As[ka * SA + ra + mt * 16];
                af[mt][1] = As[ka * SA + ra + mt * 16 + 8];
                af[mt][2] = As[(ka + 4) * SA + ra + mt * 16];
                af[mt][3] = As[(ka + 4) * SA + ra + mt * 16 + 8];
            }
            const int nb = wn * 32 + (lane >> 2);
            uint32_t bf[4][2];
            #pragma unroll
            for (int nt = 0; nt < 4; nt++) {
                bf[nt][0] = Bs[ka * SB + nb + nt * 8];
                bf[nt][1] = Bs[(ka + 4) * SB + nb + nt * 8];
            }
            #pragma unroll
            for (int mt = 0; mt < 2; mt++)
                #pragma unroll
                for (int nt = 0; nt < 4; nt++)
                    mma_tf32(acc[mt][nt], af[mt], bf[nt]);
        }
        __syncthreads();
    }

    // epilogue: permute into d_qkv[b][which][h][n][d]
    #pragma unroll
    for (int mt = 0; mt < 2; mt++) {
        #pragma unroll
        for (int half = 0; half < 2; half++) {
            int mg = m0 + wm * 32 + mt * 16 + (lane >> 2) + half * 8;
            int bb = mg / NTOK;
            int nn = mg - bb * NTOK;
            #pragma unroll
            for (int nt = 0; nt < 4; nt++) {
                int c = n0 + wn * 32 + nt * 8 + (lane & 3) * 2;
                int which = c / EMB;
                int rem = c - which * EMB;
                int h = rem >> 5;
                int d = rem & 31;
                size_t dst = ((((size_t)bb * 3 + which) * NHEADS + h) * NTOK + nn) * HDIM + d;
                float v0 = acc[mt][nt][half * 2 + 0] + bias[c];
                float v1 = acc[mt][nt][half * 2 + 1] + bias[c + 1];
                *(float2*)&d_qkv[dst] = make_float2(v0, v1);
            }
        }
    }
}

// Projection variant: plain row-major store to out
__global__ __launch_bounds__(256) void gemm_proj_kernel(
    const float* __restrict__ W, const float* __restrict__ bias,
    float* __restrict__ out) {
    __shared__ uint32_t As[32 * SA];
    __shared__ uint32_t Bs[32 * SB];

    const int tid = threadIdx.x;
    const int lane = tid & 31;
    const int wid = tid >> 5;
    const int wm = wid >> 1;
    const int wn = wid & 1;
    const int m0 = blockIdx.y * 128;
    const int n0 = blockIdx.x * 64;

    const int lm  = tid & 127;
    const int lka = (tid >> 7) * 16;
    const int ln  = tid & 63;
    const int lkb = (tid >> 6) * 8;

    float acc[2][4][4];
    #pragma unroll
    for (int mt = 0; mt < 2; mt++)
        #pragma unroll
        for (int nt = 0; nt < 4; nt++)
            #pragma unroll
            for (int r = 0; r < 4; r++) acc[mt][nt][r] = 0.f;

    const float* ap = d_attnout + (size_t)(m0 + lm) * EMB + lka;
    const float* bp = W + (size_t)(n0 + ln) * EMB + lkb;

    for (int kt = 0; kt < EMB; kt += 32) {
        #pragma unroll
        for (int q = 0; q < 4; q++) {
            float4 v = *(const float4*)(ap + kt + q * 4);
            int k = lka + q * 4;
            As[(k + 0) * SA + lm] = f2tf32(v.x);
            As[(k + 1) * SA + lm] = f2tf32(v.y);
            As[(k + 2) * SA + lm] = f2tf32(v.z);
            As[(k + 3) * SA + lm] = f2tf32(v.w);
        }
        #pragma unroll
        for (int q = 0; q < 2; q++) {
            float4 v = *(const float4*)(bp + kt + q * 4);
            int k = lkb + q * 4;
            Bs[(k + 0) * SB + ln] = f2tf32(v.x);
            Bs[(k + 1) * SB + ln] = f2tf32(v.y);
            Bs[(k + 2) * SB + ln] = f2tf32(v.z);
            Bs[(k + 3) * SB + ln] = f2tf32(v.w);
        }
        __syncthreads();
        #pragma unroll
        for (int ks = 0; ks < 32; ks += 8) {
            const int ka = ks + (lane & 3);
            const int ra = wm * 32 + (lane >> 2);
            uint32_t af[2][4];
            #pragma unroll
            for (int mt = 0; mt < 2; mt++) {
                af[mt][0] = As[ka * SA + ra + mt * 16];
                af[mt][1] = As[ka * SA + ra + mt * 16 + 8];
                af[mt][2] = As[(ka + 4) * SA + ra + mt * 16];
                af[mt][3] = As[(ka + 4) * SA + ra + mt * 16 + 8];
            }
            const int nb = wn * 32 + (lane >> 2);
            uint32_t bf[4][2];
            #pragma unroll
            for (int nt = 0; nt < 4; nt++) {
                bf[nt][0] = Bs[ka * SB + nb + nt * 8];
                bf[nt][1] = Bs[(ka + 4) * SB + nb + nt * 8];
            }
            #pragma unroll
            for (int mt = 0; mt < 2; mt++)
                #pragma unroll
                for (int nt = 0; nt < 4; nt++)
                    mma_tf32(acc[mt][nt], af[mt], bf[nt]);
        }
        __syncthreads();
    }

    #pragma unroll
    for (int mt = 0; mt < 2; mt++) {
        #pragma unroll
        for (int half = 0; half < 2; half++) {
            int mg = m0 + wm * 32 + mt * 16 + (lane >> 2) + half * 8;
            #pragma unroll
            for (int nt = 0; nt < 4; nt++) {
                int c = n0 + wn * 32 + nt * 8 + (lane & 3) * 2;
                float v0 = acc[mt][nt][half * 2 + 0] + bias[c];
                float v1 = acc[mt][nt][half * 2 + 1] + bias[c + 1];
                *(float2*)&out[(size_t)mg * EMB + c] = make_float2(v0, v1);
            }
        }
    }
}

// ---------------------------------------------------------------------------
// Kernel 3: fused attention per (b, h). Chunked online softmax — NO spills.
// 7 chunks of 14 scores; running (max, sum, o[32]) rescaled per chunk.
// ---------------------------------------------------------------------------
#define SPAD 36
#define CHUNK 14
#define NCHUNK 7

__global__ __launch_bounds__(128) void attn_kernel() {
    __shared__ __align__(16) float sh[3 * NTOK * SPAD];
    float* qs = sh;
    float* ks = sh + NTOK * SPAD;
    float* vs = sh + 2 * NTOK * SPAD;

    const int bh = blockIdx.x;
    const int b = bh / NHEADS;
    const int h = bh - b * NHEADS;
    const int w = b & (NWIN - 1);

    const size_t base = (((size_t)b * 3) * NHEADS + h) * (NTOK * HDIM);
    const float* qg = d_qkv + base;
    const float* kg = qg + (size_t)NHEADS * NTOK * HDIM;
    const float* vg = qg + 2 * (size_t)NHEADS * NTOK * HDIM;

    for (int idx = threadIdx.x; idx < NTOK * HDIM; idx += 128) {
        int n = idx >> 5, d = idx & 31;
        qs[n * SPAD + d] = qg[idx];
        ks[n * SPAD + d] = kg[idx];
        vs[n * SPAD + d] = vg[idx];
    }
    __syncthreads();

    const int i = threadIdx.x;
    if (i < NTOK) {
        float qr[HDIM];
        #pragma unroll
        for (int d = 0; d < HDIM; d++) qr[d] = qs[i * SPAD + d];

        const float2* bm2 = (const float2*)(d_bm + ((size_t)(h * NWIN + w) * NN + (size_t)i * NTOK));
        const float scale = 0.17677669529663687f;  // 32^-0.5

        float m_run = -1e30f, l_run = 0.f;
        float o[HDIM];
        #pragma unroll
        for (int d = 0; d < HDIM; d++) o[d] = 0.f;

        for (int c = 0; c < NCHUNK; c++) {
            const int j0 = c * CHUNK;
            float2 bmv[CHUNK / 2];
            #pragma unroll
            for (int t = 0; t < CHUNK / 2; t++) bmv[t] = bm2[c * (CHUNK / 2) + t];

            float s[CHUNK];
            float cmax = -1e30f;
            #pragma unroll
            for (int jj = 0; jj < CHUNK; jj++) {
                const int j = j0 + jj;
                float acc = 0.f;
                #pragma unroll
                for (int d4 = 0; d4 < 8; d4++) {
                    float4 kv = *(const float4*)&ks[j * SPAD + d4 * 4];
                    acc = fmaf(qr[d4 * 4 + 0], kv.x, acc);
                    acc = fmaf(qr[d4 * 4 + 1], kv.y, acc);
                    acc = fmaf(qr[d4 * 4 + 2], kv.z, acc);
                    acc = fmaf(qr[d4 * 4 + 3], kv.w, acc);
                }
                float bmval = (jj & 1) ? bmv[jj >> 1].y : bmv[jj >> 1].x;
                float val = fmaf(acc, scale, bmval);
                s[jj] = val;
                cmax = fmaxf(cmax, val);
            }
            float nm = fmaxf(m_run, cmax);
            float corr = __expf(m_run - nm);   // 0 on first chunk
            l_run *= corr;
            #pragma unroll
            for (int d = 0; d < HDIM; d++) o[d] *= corr;
            #pragma unroll
            for (int jj = 0; jj < CHUNK; jj++) {
                const int j = j0 + jj;
                float p = __expf(s[jj] - nm);
                l_run += p;
                #pragma unroll
                for (int d4 = 0; d4 < 8; d4++) {
                    float4 vv = *(const float4*)&vs[j * SPAD + d4 * 4];
                    o[d4 * 4 + 0] = fmaf(p, vv.x, o[d4 * 4 + 0]);
                    o[d4 * 4 + 1] = fmaf(p, vv.y, o[d4 * 4 + 1]);
                    o[d4 * 4 + 2] = fmaf(p, vv.z, o[d4 * 4 + 2]);
                    o[d4 * 4 + 3] = fmaf(p, vv.w, o[d4 * 4 + 3]);
                }
            }
            m_run = nm;
        }

        float inv = 1.f / l_run;
        float* op = d_attnout + ((size_t)b * NTOK + i) * EMB + h * HDIM;
        #pragma unroll
        for (int d4 = 0; d4 < 8; d4++) {
            float4 r;
            r.x = o[d4 * 4 + 0] * inv;
            r.y = o[d4 * 4 + 1] * inv;
            r.z = o[d4 * 4 + 2] * inv;
            r.w = o[d4 * 4 + 3] * inv;
            *(float4*)(op + d4 * 4) = r;
        }
    }
}

// ---------------------------------------------------------------------------
// Launch
// ---------------------------------------------------------------------------
extern "C" void kernel_launch(void* const* d_in, const int* in_sizes, int n_in,
                              void* d_out, int out_size) {
    const float* x          = (const float*)d_in[0];
    const float* mask       = (const float*)d_in[1];
    const float* qkv_w      = (const float*)d_in[2];
    const float* qkv_b      = (const float*)d_in[3];
    const float* o_w        = (const float*)d_in[4];
    const float* o_b        = (const float*)d_in[5];
    const float* bias_table = (const float*)d_in[6];
    const int*   rel_index  = (const int*)d_in[7];
    float* out = (float*)d_out;

    combine_bias_kernel<<<dim3(10, NHEADS, NWIN), 256>>>(bias_table, rel_index, mask);

    // QKV: M = 200704 (1568 tiles of 128), Ncols = 576 (9 tiles of 64)
    gemm_qkv_kernel<<<dim3(9, 1568), 256>>>(x, qkv_w, qkv_b);

    // Attention: one block per (batch, head)
    attn_kernel<<<BATCH * NHEADS, 128>>>();

    // Projection: Ncols = 192 (3 tiles of 64)
    gemm_proj_kernel<<<dim3(3, 1568), 256>>>(o_w, o_b, out);
}

// round 8
// speedup vs baseline: 2.5284x; 1.3138x over previous
#include <cuda_runtime.h>
#include <cstddef>
#include <cstdint>

// Problem constants
#define BATCH   2048
#define NTOK    98
#define EMB     192
#define NHEADS  6
#define HDIM    32
#define NWIN    64
#define NN      (NTOK*NTOK)        // 9604

// Scratch (device globals — no allocation allowed)
__device__ float d_qkv[(size_t)BATCH * 3 * NHEADS * NTOK * HDIM];   // [b][which][h][n][d]
__device__ float d_attnout[(size_t)BATCH * NTOK * EMB];             // [b][n][h*32+d]
__device__ float d_bm[(size_t)NHEADS * NWIN * NN];                  // bias+mask combined

// ---------------------------------------------------------------------------
// helpers
// ---------------------------------------------------------------------------
__device__ __forceinline__ uint32_t f2tf32(float f) {
    uint32_t u;
    asm("cvt.rna.tf32.f32 %0, %1;" : "=r"(u) : "f"(f));
    return u;
}

__device__ __forceinline__ void mma_tf32(float c[4], const uint32_t a[4], const uint32_t b[2]) {
    asm volatile(
        "mma.sync.aligned.m16n8k8.row.col.f32.tf32.tf32.f32 "
        "{%0,%1,%2,%3},{%4,%5,%6,%7},{%8,%9},{%0,%1,%2,%3};"
        : "+f"(c[0]), "+f"(c[1]), "+f"(c[2]), "+f"(c[3])
        : "r"(a[0]), "r"(a[1]), "r"(a[2]), "r"(a[3]), "r"(b[0]), "r"(b[1]));
}

__device__ __forceinline__ void cp16(uint32_t dst, const void* src) {
    asm volatile("cp.async.cg.shared.global [%0], [%1], 16;" :: "r"(dst), "l"(src));
}
__device__ __forceinline__ void cp_commit() {
    asm volatile("cp.async.commit_group;");
}
template <int N> __device__ __forceinline__ void cp_wait() {
    asm volatile("cp.async.wait_group %0;" :: "n"(N));
}

// ---------------------------------------------------------------------------
// Kernel 1: combine bias + mask:  d_bm[h][w][i][j] = table[rel[i,j]*6+h] + mask[w][i][j]
// ---------------------------------------------------------------------------
__global__ void combine_bias_kernel(const float* __restrict__ table,
                                    const int* __restrict__ rel,
                                    const float* __restrict__ mask) {
    const int h = blockIdx.y;
    const int w = blockIdx.z;
    const float* mrow = mask + (size_t)w * NN;
    float* dst = d_bm + ((size_t)(h * NWIN + w)) * NN;
    for (int idx = blockIdx.x * blockDim.x + threadIdx.x; idx < NN;
         idx += gridDim.x * blockDim.x) {
        dst[idx] = table[rel[idx] * NHEADS + h] + mrow[idx];
    }
}

// ---------------------------------------------------------------------------
// tf32 tensor-core GEMM: C[m, c] = A[m,:] . W[c,:] + bias[c]
// Block tile 256x64, K-tile 32, 256 threads = 8 warps (4m x 2n), warp 64x32.
// cp.async.cg double-buffered; smem row-major [row][k], stride 36 floats
// (conflict-free fragment LDS: bank = 4*(lane>>2) + (lane&3), all distinct).
// ---------------------------------------------------------------------------
#define KTILE 32
#define NKIT  6          // 192 / 32
#define ASTR  36
#define BSTR  36
#define AS_FLOATS (256 * ASTR)   // 9216
#define BS_FLOATS (64 * BSTR)    // 2304
#define GEMM_SMEM_BYTES ((AS_FLOATS + BS_FLOATS) * 2 * 4)  // 92160

__device__ __forceinline__ void g_load_tiles(const float* __restrict__ A,
                                             const float* __restrict__ W,
                                             float* As, float* Bs,
                                             int m0, int n0, int kt, int tid) {
    const int r = tid >> 3;       // 0..31
    const int q = tid & 7;        // 16B chunk within 128B row-slice
    uint32_t as_base = (uint32_t)__cvta_generic_to_shared(As);
    uint32_t bs_base = (uint32_t)__cvta_generic_to_shared(Bs);
    #pragma unroll
    for (int it = 0; it < 8; it++) {
        int m = r + it * 32;
        cp16(as_base + (uint32_t)(m * ASTR + q * 4) * 4,
             A + (size_t)(m0 + m) * EMB + kt + q * 4);
    }
    #pragma unroll
    for (int it = 0; it < 2; it++) {
        int n = r + it * 32;
        cp16(bs_base + (uint32_t)(n * BSTR + q * 4) * 4,
             W + (size_t)(n0 + n) * EMB + kt + q * 4);
    }
    cp_commit();
}

__device__ __forceinline__ void g_compute(const float* As, const float* Bs,
                                          float acc[4][4][4], int lane,
                                          int wm, int wn) {
    #pragma unroll
    for (int ks = 0; ks < KTILE; ks += 8) {
        const int ka = ks + (lane & 3);
        uint32_t af[4][4];
        #pragma unroll
        for (int mt = 0; mt < 4; mt++) {
            const float* ap = As + (wm * 64 + mt * 16 + (lane >> 2)) * ASTR;
            af[mt][0] = f2tf32(ap[ka]);
            af[mt][1] = f2tf32(ap[8 * ASTR + ka]);
            af[mt][2] = f2tf32(ap[ka + 4]);
            af[mt][3] = f2tf32(ap[8 * ASTR + ka + 4]);
        }
        uint32_t bf[4][2];
        #pragma unroll
        for (int nt = 0; nt < 4; nt++) {
            const float* bp = Bs + (wn * 32 + nt * 8 + (lane >> 2)) * BSTR;
            bf[nt][0] = f2tf32(bp[ka]);
            bf[nt][1] = f2tf32(bp[ka + 4]);
        }
        #pragma unroll
        for (int mt = 0; mt < 4; mt++)
            #pragma unroll
            for (int nt = 0; nt < 4; nt++)
                mma_tf32(acc[mt][nt], af[mt], bf[nt]);
    }
}

// QKV variant: epilogue permutes into d_qkv[b][which][h][n][d]
__global__ __launch_bounds__(256, 2) void gemm_qkv_kernel(
    const float* __restrict__ A, const float* __restrict__ W,
    const float* __restrict__ bias) {
    extern __shared__ float sm[];
    float* As[2] = { sm, sm + AS_FLOATS };
    float* Bs[2] = { sm + 2 * AS_FLOATS, sm + 2 * AS_FLOATS + BS_FLOATS };

    const int tid = threadIdx.x;
    const int lane = tid & 31;
    const int wid = tid >> 5;
    const int wm = wid >> 1;
    const int wn = wid & 1;
    const int m0 = blockIdx.y * 256;
    const int n0 = blockIdx.x * 64;

    float acc[4][4][4];
    #pragma unroll
    for (int mt = 0; mt < 4; mt++)
        #pragma unroll
        for (int nt = 0; nt < 4; nt++)
            #pragma unroll
            for (int r = 0; r < 4; r++) acc[mt][nt][r] = 0.f;

    g_load_tiles(A, W, As[0], Bs[0], m0, n0, 0, tid);
    g_load_tiles(A, W, As[1], Bs[1], m0, n0, KTILE, tid);

    #pragma unroll
    for (int it = 0; it < NKIT; it++) {
        if (it < NKIT - 1) cp_wait<1>(); else cp_wait<0>();
        __syncthreads();
        g_compute(As[it & 1], Bs[it & 1], acc, lane, wm, wn);
        __syncthreads();
        if (it + 2 < NKIT)
            g_load_tiles(A, W, As[it & 1], Bs[it & 1], m0, n0, (it + 2) * KTILE, tid);
    }

    #pragma unroll
    for (int mt = 0; mt < 4; mt++) {
        #pragma unroll
        for (int half = 0; half < 2; half++) {
            int mg = m0 + wm * 64 + mt * 16 + (lane >> 2) + half * 8;
            int bb = mg / NTOK;
            int nn = mg - bb * NTOK;
            #pragma unroll
            for (int nt = 0; nt < 4; nt++) {
                int c = n0 + wn * 32 + nt * 8 + (lane & 3) * 2;
                int which = c / EMB;
                int rem = c - which * EMB;
                int h = rem >> 5;
                int d = rem & 31;
                size_t dst = ((((size_t)bb * 3 + which) * NHEADS + h) * NTOK + nn) * HDIM + d;
                float v0 = acc[mt][nt][half * 2 + 0] + bias[c];
                float v1 = acc[mt][nt][half * 2 + 1] + bias[c + 1];
                *(float2*)&d_qkv[dst] = make_float2(v0, v1);
            }
        }
    }
}

// Projection variant: plain row-major store
__global__ __launch_bounds__(256, 2) void gemm_proj_kernel(
    const float* __restrict__ W, const float* __restrict__ bias,
    float* __restrict__ out) {
    extern __shared__ float sm[];
    float* As[2] = { sm, sm + AS_FLOATS };
    float* Bs[2] = { sm + 2 * AS_FLOATS, sm + 2 * AS_FLOATS + BS_FLOATS };

    const int tid = threadIdx.x;
    const int lane = tid & 31;
    const int wid = tid >> 5;
    const int wm = wid >> 1;
    const int wn = wid & 1;
    const int m0 = blockIdx.y * 256;
    const int n0 = blockIdx.x * 64;

    float acc[4][4][4];
    #pragma unroll
    for (int mt = 0; mt < 4; mt++)
        #pragma unroll
        for (int nt = 0; nt < 4; nt++)
            #pragma unroll
            for (int r = 0; r < 4; r++) acc[mt][nt][r] = 0.f;

    const float* A = d_attnout;
    g_load_tiles(A, W, As[0], Bs[0], m0, n0, 0, tid);
    g_load_tiles(A, W, As[1], Bs[1], m0, n0, KTILE, tid);

    #pragma unroll
    for (int it = 0; it < NKIT; it++) {
        if (it < NKIT - 1) cp_wait<1>(); else cp_wait<0>();
        __syncthreads();
        g_compute(As[it & 1], Bs[it & 1], acc, lane, wm, wn);
        __syncthreads();
        if (it + 2 < NKIT)
            g_load_tiles(A, W, As[it & 1], Bs[it & 1], m0, n0, (it + 2) * KTILE, tid);
    }

    #pragma unroll
    for (int mt = 0; mt < 4; mt++) {
        #pragma unroll
        for (int half = 0; half < 2; half++) {
            int mg = m0 + wm * 64 + mt * 16 + (lane >> 2) + half * 8;
            #pragma unroll
            for (int nt = 0; nt < 4; nt++) {
                int c = n0 + wn * 32 + nt * 8 + (lane & 3) * 2;
                float v0 = acc[mt][nt][half * 2 + 0] + bias[c];
                float v1 = acc[mt][nt][half * 2 + 1] + bias[c + 1];
                *(float2*)&out[(size_t)mg * EMB + c] = make_float2(v0, v1);
            }
        }
    }
}

// ---------------------------------------------------------------------------
// Kernel 3: fused attention, 4 (b,h) heads per block. Chunked online softmax.
// 416 threads: thread t -> head slot t/98, query t%98 (392 active, 94.2%).
// ---------------------------------------------------------------------------
#define SPAD 36
#define CHUNK 14
#define NCHUNK 7
#define HB 4
#define ATHREADS 416
#define HEADSZ (3 * NTOK * SPAD)                 // floats per head (q,k,v)
#define ATTN_SMEM_BYTES (HB * HEADSZ * 4)        // 169344

__global__ __launch_bounds__(ATHREADS, 1) void attn_kernel() {
    extern __shared__ float sh[];
    const int t = threadIdx.x;

    // cooperative load: HB heads x 3 arrays x 784 float4 chunks
    for (int idx = t; idx < HB * 3 * (NTOK * HDIM / 4); idx += ATHREADS) {
        int h2 = idx / (3 * 784);
        int rem = idx - h2 * (3 * 784);
        int arr = rem / 784;
        int e = rem - arr * 784;
        int n = e >> 3, dq = (e & 7) * 4;
        int bh = blockIdx.x * HB + h2;
        int b = bh / NHEADS, h = bh - b * NHEADS;
        const float* src = d_qkv + ((((size_t)b * 3 + arr) * NHEADS + h) * NTOK + n) * HDIM + dq;
        *(float4*)&sh[h2 * HEADSZ + arr * (NTOK * SPAD) + n * SPAD + dq] =
            *(const float4*)src;
    }
    __syncthreads();

    const int hl = t / NTOK;
    const int i = t - hl * NTOK;
    if (hl < HB) {
        const float* qs = sh + hl * HEADSZ;
        const float* ks = qs + NTOK * SPAD;
        const float* vs = qs + 2 * NTOK * SPAD;

        const int bh = blockIdx.x * HB + hl;
        const int b = bh / NHEADS;
        const int h = bh - b * NHEADS;
        const int w = b & (NWIN - 1);

        float qr[HDIM];
        #pragma unroll
        for (int d = 0; d < HDIM; d++) qr[d] = qs[i * SPAD + d];

        const float2* bm2 = (const float2*)(d_bm + ((size_t)(h * NWIN + w) * NN + (size_t)i * NTOK));
        const float scale = 0.17677669529663687f;  // 32^-0.5

        float m_run = -1e30f, l_run = 0.f;
        float o[HDIM];
        #pragma unroll
        for (int d = 0; d < HDIM; d++) o[d] = 0.f;

        for (int c = 0; c < NCHUNK; c++) {
            const int j0 = c * CHUNK;
            float2 bmv[CHUNK / 2];
            #pragma unroll
            for (int tt = 0; tt < CHUNK / 2; tt++) bmv[tt] = bm2[c * (CHUNK / 2) + tt];

            float s[CHUNK];
            float cmax = -1e30f;
            #pragma unroll
            for (int jj = 0; jj < CHUNK; jj++) {
                const int j = j0 + jj;
                float acc = 0.f;
                #pragma unroll
                for (int d4 = 0; d4 < 8; d4++) {
                    float4 kv = *(const float4*)&ks[j * SPAD + d4 * 4];
                    acc = fmaf(qr[d4 * 4 + 0], kv.x, acc);
                    acc = fmaf(qr[d4 * 4 + 1], kv.y, acc);
                    acc = fmaf(qr[d4 * 4 + 2], kv.z, acc);
                    acc = fmaf(qr[d4 * 4 + 3], kv.w, acc);
                }
                float bmval = (jj & 1) ? bmv[jj >> 1].y : bmv[jj >> 1].x;
                float val = fmaf(acc, scale, bmval);
                s[jj] = val;
                cmax = fmaxf(cmax, val);
            }
            float nm = fmaxf(m_run, cmax);
            float corr = __expf(m_run - nm);   // 0 on first chunk
            l_run *= corr;
            #pragma unroll
            for (int d = 0; d < HDIM; d++) o[d] *= corr;
            #pragma unroll
            for (int jj = 0; jj < CHUNK; jj++) {
                const int j = j0 + jj;
                float p = __expf(s[jj] - nm);
                l_run += p;
                #pragma unroll
                for (int d4 = 0; d4 < 8; d4++) {
                    float4 vv = *(const float4*)&vs[j * SPAD + d4 * 4];
                    o[d4 * 4 + 0] = fmaf(p, vv.x, o[d4 * 4 + 0]);
                    o[d4 * 4 + 1] = fmaf(p, vv.y, o[d4 * 4 + 1]);
                    o[d4 * 4 + 2] = fmaf(p, vv.z, o[d4 * 4 + 2]);
                    o[d4 * 4 + 3] = fmaf(p, vv.w, o[d4 * 4 + 3]);
                }
            }
            m_run = nm;
        }

        float inv = 1.f / l_run;
        float* op = d_attnout + ((size_t)b * NTOK + i) * EMB + h * HDIM;
        #pragma unroll
        for (int d4 = 0; d4 < 8; d4++) {
            float4 r;
            r.x = o[d4 * 4 + 0] * inv;
            r.y = o[d4 * 4 + 1] * inv;
            r.z = o[d4 * 4 + 2] * inv;
            r.w = o[d4 * 4 + 3] * inv;
            *(float4*)(op + d4 * 4) = r;
        }
    }
}

// ---------------------------------------------------------------------------
// Launch
// ---------------------------------------------------------------------------
extern "C" void kernel_launch(void* const* d_in, const int* in_sizes, int n_in,
                              void* d_out, int out_size) {
    const float* x          = (const float*)d_in[0];
    const float* mask       = (const float*)d_in[1];
    const float* qkv_w      = (const float*)d_in[2];
    const float* qkv_b      = (const float*)d_in[3];
    const float* o_w        = (const float*)d_in[4];
    const float* o_b        = (const float*)d_in[5];
    const float* bias_table = (const float*)d_in[6];
    const int*   rel_index  = (const int*)d_in[7];
    float* out = (float*)d_out;

    cudaFuncSetAttribute(gemm_qkv_kernel,
        cudaFuncAttributeMaxDynamicSharedMemorySize, GEMM_SMEM_BYTES);
    cudaFuncSetAttribute(gemm_proj_kernel,
        cudaFuncAttributeMaxDynamicSharedMemorySize, GEMM_SMEM_BYTES);
    cudaFuncSetAttribute(attn_kernel,
        cudaFuncAttributeMaxDynamicSharedMemorySize, ATTN_SMEM_BYTES);

    combine_bias_kernel<<<dim3(10, NHEADS, NWIN), 256>>>(bias_table, rel_index, mask);

    // QKV: M = 200704 (784 tiles of 256), Ncols = 576 (9 tiles of 64)
    gemm_qkv_kernel<<<dim3(9, 784), 256, GEMM_SMEM_BYTES>>>(x, qkv_w, qkv_b);

    // Attention: 4 heads per block, 12288/4 = 3072 blocks
    attn_kernel<<<3072, ATHREADS, ATTN_SMEM_BYTES>>>();

    // Projection: Ncols = 192 (3 tiles of 64)
    gemm_proj_kernel<<<dim3(3, 784), 256, GEMM_SMEM_BYTES>>>(o_w, o_b, out);
}

// round 9
// speedup vs baseline: 4.4425x; 1.7571x over previous
#include <cuda_runtime.h>
#include <cstddef>
#include <cstdint>

// Problem constants
#define BATCH   2048
#define NTOK    98
#define EMB     192
#define NHEADS  6
#define HDIM    32
#define NWIN    64
#define NN      (NTOK*NTOK)        // 9604
#define NCP     112                // padded key/col dim for attention tiles
#define NNP     (NTOK*NCP)         // 10976 padded bm row block

// Scratch (device globals — no allocation allowed)
__device__ float d_qkv[(size_t)BATCH * 3 * NHEADS * NTOK * HDIM];   // [b][which][h][n][d]
__device__ float d_attnout[(size_t)BATCH * NTOK * EMB];             // [b][n][h*32+d]
__device__ float d_bm[(size_t)NHEADS * NWIN * NNP];                 // bias+mask, padded cols

// ---------------------------------------------------------------------------
// helpers
// ---------------------------------------------------------------------------
__device__ __forceinline__ uint32_t f2tf32(float f) {
    uint32_t u;
    asm("cvt.rna.tf32.f32 %0, %1;" : "=r"(u) : "f"(f));
    return u;
}

__device__ __forceinline__ void mma_tf32(float c[4], const uint32_t a[4], const uint32_t b[2]) {
    asm volatile(
        "mma.sync.aligned.m16n8k8.row.col.f32.tf32.tf32.f32 "
        "{%0,%1,%2,%3},{%4,%5,%6,%7},{%8,%9},{%0,%1,%2,%3};"
        : "+f"(c[0]), "+f"(c[1]), "+f"(c[2]), "+f"(c[3])
        : "r"(a[0]), "r"(a[1]), "r"(a[2]), "r"(a[3]), "r"(b[0]), "r"(b[1]));
}

__device__ __forceinline__ void cp16(uint32_t dst, const void* src) {
    asm volatile("cp.async.cg.shared.global [%0], [%1], 16;" :: "r"(dst), "l"(src));
}
__device__ __forceinline__ void cp_commit() {
    asm volatile("cp.async.commit_group;");
}
template <int N> __device__ __forceinline__ void cp_wait() {
    asm volatile("cp.async.wait_group %0;" :: "n"(N));
}

// ---------------------------------------------------------------------------
// Kernel 1: combine bias + mask with column padding to NCP:
//   d_bm[h][w][i][j] = table[rel[i,j]*6+h] + mask[w][i][j]   (j < 98)
//                    = -1e30                                  (98 <= j < 112)
// ---------------------------------------------------------------------------
__global__ void combine_bias_kernel(const float* __restrict__ table,
                                    const int* __restrict__ rel,
                                    const float* __restrict__ mask) {
    const int h = blockIdx.y;
    const int w = blockIdx.z;
    const int idx = blockIdx.x * blockDim.x + threadIdx.x;
    if (idx >= NNP) return;
    const int i = idx / NCP;
    const int j = idx - i * NCP;
    float v = -1e30f;
    if (j < NTOK)
        v = table[rel[i * NTOK + j] * NHEADS + h] + mask[(size_t)w * NN + i * NTOK + j];
    d_bm[((size_t)(h * NWIN + w)) * NNP + idx] = v;
}

// ---------------------------------------------------------------------------
// tf32 tensor-core GEMM (unchanged from round 8)
// ---------------------------------------------------------------------------
#define KTILE 32
#define NKIT  6
#define ASTR  36
#define BSTR  36
#define AS_FLOATS (256 * ASTR)
#define BS_FLOATS (64 * BSTR)
#define GEMM_SMEM_BYTES ((AS_FLOATS + BS_FLOATS) * 2 * 4)

__device__ __forceinline__ void g_load_tiles(const float* __restrict__ A,
                                             const float* __restrict__ W,
                                             float* As, float* Bs,
                                             int m0, int n0, int kt, int tid) {
    const int r = tid >> 3;
    const int q = tid & 7;
    uint32_t as_base = (uint32_t)__cvta_generic_to_shared(As);
    uint32_t bs_base = (uint32_t)__cvta_generic_to_shared(Bs);
    #pragma unroll
    for (int it = 0; it < 8; it++) {
        int m = r + it * 32;
        cp16(as_base + (uint32_t)(m * ASTR + q * 4) * 4,
             A + (size_t)(m0 + m) * EMB + kt + q * 4);
    }
    #pragma unroll
    for (int it = 0; it < 2; it++) {
        int n = r + it * 32;
        cp16(bs_base + (uint32_t)(n * BSTR + q * 4) * 4,
             W + (size_t)(n0 + n) * EMB + kt + q * 4);
    }
    cp_commit();
}

__device__ __forceinline__ void g_compute(const float* As, const float* Bs,
                                          float acc[4][4][4], int lane,
                                          int wm, int wn) {
    #pragma unroll
    for (int ks = 0; ks < KTILE; ks += 8) {
        const int ka = ks + (lane & 3);
        uint32_t af[4][4];
        #pragma unroll
        for (int mt = 0; mt < 4; mt++) {
            const float* ap = As + (wm * 64 + mt * 16 + (lane >> 2)) * ASTR;
            af[mt][0] = f2tf32(ap[ka]);
            af[mt][1] = f2tf32(ap[8 * ASTR + ka]);
            af[mt][2] = f2tf32(ap[ka + 4]);
            af[mt][3] = f2tf32(ap[8 * ASTR + ka + 4]);
        }
        uint32_t bf[4][2];
        #pragma unroll
        for (int nt = 0; nt < 4; nt++) {
            const float* bp = Bs + (wn * 32 + nt * 8 + (lane >> 2)) * BSTR;
            bf[nt][0] = f2tf32(bp[ka]);
            bf[nt][1] = f2tf32(bp[ka + 4]);
        }
        #pragma unroll
        for (int mt = 0; mt < 4; mt++)
            #pragma unroll
            for (int nt = 0; nt < 4; nt++)
                mma_tf32(acc[mt][nt], af[mt], bf[nt]);
    }
}

__global__ __launch_bounds__(256, 2) void gemm_qkv_kernel(
    const float* __restrict__ A, const float* __restrict__ W,
    const float* __restrict__ bias) {
    extern __shared__ float sm[];
    float* As[2] = { sm, sm + AS_FLOATS };
    float* Bs[2] = { sm + 2 * AS_FLOATS, sm + 2 * AS_FLOATS + BS_FLOATS };

    const int tid = threadIdx.x;
    const int lane = tid & 31;
    const int wid = tid >> 5;
    const int wm = wid >> 1;
    const int wn = wid & 1;
    const int m0 = blockIdx.y * 256;
    const int n0 = blockIdx.x * 64;

    float acc[4][4][4];
    #pragma unroll
    for (int mt = 0; mt < 4; mt++)
        #pragma unroll
        for (int nt = 0; nt < 4; nt++)
            #pragma unroll
            for (int r = 0; r < 4; r++) acc[mt][nt][r] = 0.f;

    g_load_tiles(A, W, As[0], Bs[0], m0, n0, 0, tid);
    g_load_tiles(A, W, As[1], Bs[1], m0, n0, KTILE, tid);

    #pragma unroll
    for (int it = 0; it < NKIT; it++) {
        if (it < NKIT - 1) cp_wait<1>(); else cp_wait<0>();
        __syncthreads();
        g_compute(As[it & 1], Bs[it & 1], acc, lane, wm, wn);
        __syncthreads();
        if (it + 2 < NKIT)
            g_load_tiles(A, W, As[it & 1], Bs[it & 1], m0, n0, (it + 2) * KTILE, tid);
    }

    #pragma unroll
    for (int mt = 0; mt < 4; mt++) {
        #pragma unroll
        for (int half = 0; half < 2; half++) {
            int mg = m0 + wm * 64 + mt * 16 + (lane >> 2) + half * 8;
            int bb = mg / NTOK;
            int nn = mg - bb * NTOK;
            #pragma unroll
            for (int nt = 0; nt < 4; nt++) {
                int c = n0 + wn * 32 + nt * 8 + (lane & 3) * 2;
                int which = c / EMB;
                int rem = c - which * EMB;
                int h = rem >> 5;
                int d = rem & 31;
                size_t dst = ((((size_t)bb * 3 + which) * NHEADS + h) * NTOK + nn) * HDIM + d;
                float v0 = acc[mt][nt][half * 2 + 0] + bias[c];
                float v1 = acc[mt][nt][half * 2 + 1] + bias[c + 1];
                *(float2*)&d_qkv[dst] = make_float2(v0, v1);
            }
        }
    }
}

__global__ __launch_bounds__(256, 2) void gemm_proj_kernel(
    const float* __restrict__ W, const float* __restrict__ bias,
    float* __restrict__ out) {
    extern __shared__ float sm[];
    float* As[2] = { sm, sm + AS_FLOATS };
    float* Bs[2] = { sm + 2 * AS_FLOATS, sm + 2 * AS_FLOATS + BS_FLOATS };

    const int tid = threadIdx.x;
    const int lane = tid & 31;
    const int wid = tid >> 5;
    const int wm = wid >> 1;
    const int wn = wid & 1;
    const int m0 = blockIdx.y * 256;
    const int n0 = blockIdx.x * 64;

    float acc[4][4][4];
    #pragma unroll
    for (int mt = 0; mt < 4; mt++)
        #pragma unroll
        for (int nt = 0; nt < 4; nt++)
            #pragma unroll
            for (int r = 0; r < 4; r++) acc[mt][nt][r] = 0.f;

    const float* A = d_attnout;
    g_load_tiles(A, W, As[0], Bs[0], m0, n0, 0, tid);
    g_load_tiles(A, W, As[1], Bs[1], m0, n0, KTILE, tid);

    #pragma unroll
    for (int it = 0; it < NKIT; it++) {
        if (it < NKIT - 1) cp_wait<1>(); else cp_wait<0>();
        __syncthreads();
        g_compute(As[it & 1], Bs[it & 1], acc, lane, wm, wn);
        __syncthreads();
        if (it + 2 < NKIT)
            g_load_tiles(A, W, As[it & 1], Bs[it & 1], m0, n0, (it + 2) * KTILE, tid);
    }

    #pragma unroll
    for (int mt = 0; mt < 4; mt++) {
        #pragma unroll
        for (int half = 0; half < 2; half++) {
            int mg = m0 + wm * 64 + mt * 16 + (lane >> 2) + half * 8;
            #pragma unroll
            for (int nt = 0; nt < 4; nt++) {
                int c = n0 + wn * 32 + nt * 8 + (lane & 3) * 2;
                float v0 = acc[mt][nt][half * 2 + 0] + bias[c];
                float v1 = acc[mt][nt][half * 2 + 1] + bias[c + 1];
                *(float2*)&out[(size_t)mg * EMB + c] = make_float2(v0, v1);
            }
        }
    }
}

// ---------------------------------------------------------------------------
// Kernel 3: tensor-core attention. One CTA (128 thr, 4 warps) per (b, h).
// S = Q K^T (128x112 padded, tf32 mma, full tile in register c-frags),
// in-register softmax (quad shfl), P->A-frag permutation via shfl,
// O = P V (tf32 mma), normalized epilogue.
// ---------------------------------------------------------------------------
#define QSTR 36
#define KSTR 36
#define VSTR 40
#define SQ_FLOATS (128 * QSTR)       // 4608
#define SK_FLOATS (NCP * KSTR)       // 4032
#define SV_FLOATS (NCP * VSTR)       // 4480
#define SBM_FLOATS (NTOK * NCP)      // 10976
#define ATTN_SMEM_BYTES ((SQ_FLOATS + SK_FLOATS + SV_FLOATS + SBM_FLOATS) * 4)  // 96384

__global__ __launch_bounds__(128, 2) void attn_kernel() {
    extern __shared__ float sh[];
    float* sQ  = sh;
    float* sK  = sQ + SQ_FLOATS;
    float* sV  = sK + SK_FLOATS;
    float* sBM = sV + SV_FLOATS;

    const int t = threadIdx.x;
    const int lane = t & 31;
    const int w4 = t >> 5;          // warp 0..3

    const int bh = blockIdx.x;
    const int b = bh / NHEADS;
    const int h = bh - b * NHEADS;
    const int win = b & (NWIN - 1);

    const size_t base = (((size_t)b * 3) * NHEADS + h) * (NTOK * HDIM);
    const float* qg = d_qkv + base;
    const float* kg = qg + (size_t)NHEADS * NTOK * HDIM;
    const float* vg = qg + 2 * (size_t)NHEADS * NTOK * HDIM;
    const float* bmg = d_bm + (size_t)(h * NWIN + win) * NNP;

    // ---- stage: cp.async Q/K/V/BM, STS zeros for pad rows ----
    {
        uint32_t uQ = (uint32_t)__cvta_generic_to_shared(sQ);
        uint32_t uK = (uint32_t)__cvta_generic_to_shared(sK);
        uint32_t uV = (uint32_t)__cvta_generic_to_shared(sV);
        uint32_t uB = (uint32_t)__cvta_generic_to_shared(sBM);
        // Q/K/V: 98 rows x 8 float4 each
        for (int idx = t; idx < NTOK * 8; idx += 128) {
            int r = idx >> 3, q = (idx & 7) * 4;
            cp16(uQ + (uint32_t)(r * QSTR + q) * 4, qg + r * HDIM + q);
            cp16(uK + (uint32_t)(r * KSTR + q) * 4, kg + r * HDIM + q);
            cp16(uV + (uint32_t)(r * VSTR + q) * 4, vg + r * HDIM + q);
        }
        // BM: 98 rows x 28 float4
        for (int idx = t; idx < NTOK * 28; idx += 128) {
            int r = idx / 28, c = (idx - r * 28) * 4;
            cp16(uB + (uint32_t)(r * NCP + c) * 4, bmg + r * NCP + c);
        }
        cp_commit();
        // zero pad rows: Q rows 98..127, K rows 98..111, V rows 98..111
        float4 z = make_float4(0.f, 0.f, 0.f, 0.f);
        for (int idx = t; idx < 30 * 9; idx += 128) {
            int r = 98 + idx / 9, c = (idx % 9) * 4;
            *(float4*)&sQ[r * QSTR + c] = z;
        }
        for (int idx = t; idx < 14 * 9; idx += 128) {
            int r = 98 + idx / 9, c = (idx % 9) * 4;
            *(float4*)&sK[r * KSTR + c] = z;
        }
        for (int idx = t; idx < 14 * 10; idx += 128) {
            int r = 98 + idx / 10, c = (idx % 10) * 4;
            *(float4*)&sV[r * VSTR + c] = z;
        }
        cp_wait<0>();
        __syncthreads();
    }

    const int g = lane >> 2;        // quad row
    const int c = lane & 3;         // quad pos

    // ---- S = Q K^T : c-frags sf[2][14][4] ----
    float sf[2][14][4];
    #pragma unroll
    for (int mt = 0; mt < 2; mt++)
        #pragma unroll
        for (int nt = 0; nt < 14; nt++)
            #pragma unroll
            for (int r = 0; r < 4; r++) sf[mt][nt][r] = 0.f;

    #pragma unroll
    for (int ks = 0; ks < 4; ks++) {
        const int k = ks * 8 + c;
        uint32_t af[2][4];
        #pragma unroll
        for (int mt = 0; mt < 2; mt++) {
            const float* ap = sQ + (w4 * 32 + mt * 16 + g) * QSTR;
            af[mt][0] = f2tf32(ap[k]);
            af[mt][1] = f2tf32(ap[8 * QSTR + k]);
            af[mt][2] = f2tf32(ap[k + 4]);
            af[mt][3] = f2tf32(ap[8 * QSTR + k + 4]);
        }
        #pragma unroll
        for (int nt = 0; nt < 14; nt++) {
            const float* bp = sK + (nt * 8 + g) * KSTR;
            uint32_t bf[2];
            bf[0] = f2tf32(bp[k]);
            bf[1] = f2tf32(bp[k + 4]);
            mma_tf32(sf[0][nt], af[0], bf);
            mma_tf32(sf[1][nt], af[1], bf);
        }
    }

    // ---- scale + bias/mask add + row max ----
    const float scale = 0.17677669529663687f;  // 32^-0.5
    float mx[2][2];
    #pragma unroll
    for (int mt = 0; mt < 2; mt++) { mx[mt][0] = -1e30f; mx[mt][1] = -1e30f; }

    #pragma unroll
    for (int mt = 0; mt < 2; mt++) {
        int r0 = w4 * 32 + mt * 16 + g;
        int r0c = min(r0, NTOK - 1);
        int r1c = min(r0 + 8, NTOK - 1);
        #pragma unroll
        for (int nt = 0; nt < 14; nt++) {
            int col = nt * 8 + c * 2;
            float2 b0 = *(const float2*)&sBM[r0c * NCP + col];
            float2 b1 = *(const float2*)&sBM[r1c * NCP + col];
            sf[mt][nt][0] = fmaf(sf[mt][nt][0], scale, b0.x);
            sf[mt][nt][1] = fmaf(sf[mt][nt][1], scale, b0.y);
            sf[mt][nt][2] = fmaf(sf[mt][nt][2], scale, b1.x);
            sf[mt][nt][3] = fmaf(sf[mt][nt][3], scale, b1.y);
            mx[mt][0] = fmaxf(mx[mt][0], fmaxf(sf[mt][nt][0], sf[mt][nt][1]));
            mx[mt][1] = fmaxf(mx[mt][1], fmaxf(sf[mt][nt][2], sf[mt][nt][3]));
        }
    }
    #pragma unroll
    for (int mt = 0; mt < 2; mt++)
        #pragma unroll
        for (int hf = 0; hf < 2; hf++) {
            float v = mx[mt][hf];
            v = fmaxf(v, __shfl_xor_sync(0xffffffffu, v, 1));
            v = fmaxf(v, __shfl_xor_sync(0xffffffffu, v, 2));
            mx[mt][hf] = v;
        }

    // ---- exp + row sum ----
    float sum[2][2] = {{0.f, 0.f}, {0.f, 0.f}};
    #pragma unroll
    for (int mt = 0; mt < 2; mt++)
        #pragma unroll
        for (int nt = 0; nt < 14; nt++) {
            float p0 = __expf(sf[mt][nt][0] - mx[mt][0]);
            float p1 = __expf(sf[mt][nt][1] - mx[mt][0]);
            float p2 = __expf(sf[mt][nt][2] - mx[mt][1]);
            float p3 = __expf(sf[mt][nt][3] - mx[mt][1]);
            sf[mt][nt][0] = p0; sf[mt][nt][1] = p1;
            sf[mt][nt][2] = p2; sf[mt][nt][3] = p3;
            sum[mt][0] += p0 + p1;
            sum[mt][1] += p2 + p3;
        }
    #pragma unroll
    for (int mt = 0; mt < 2; mt++)
        #pragma unroll
        for (int hf = 0; hf < 2; hf++) {
            float v = sum[mt][hf];
            v += __shfl_xor_sync(0xffffffffu, v, 1);
            v += __shfl_xor_sync(0xffffffffu, v, 2);
            sum[mt][hf] = v;
        }

    // ---- O = P V ----
    float of[2][4][4];
    #pragma unroll
    for (int mt = 0; mt < 2; mt++)
        #pragma unroll
        for (int nt = 0; nt < 4; nt++)
            #pragma unroll
            for (int r = 0; r < 4; r++) of[mt][nt][r] = 0.f;

    const int srcA = (lane & ~3) | (c >> 1);
    const int srcB = srcA + 2;

    #pragma unroll
    for (int kt = 0; kt < 14; kt++) {
        uint32_t pa[2][4];
        #pragma unroll
        for (int mt = 0; mt < 2; mt++) {
            // permute c-frag (cols {2c,2c+1}) -> a-frag (cols {c, c+4})
            float x0 = __shfl_sync(0xffffffffu, sf[mt][kt][0], srcA);
            float x1 = __shfl_sync(0xffffffffu, sf[mt][kt][1], srcA);
            float y0 = __shfl_sync(0xffffffffu, sf[mt][kt][0], srcB);
            float y1 = __shfl_sync(0xffffffffu, sf[mt][kt][1], srcB);
            float z0 = __shfl_sync(0xffffffffu, sf[mt][kt][2], srcA);
            float z1 = __shfl_sync(0xffffffffu, sf[mt][kt][3], srcA);
            float u0 = __shfl_sync(0xffffffffu, sf[mt][kt][2], srcB);
            float u1 = __shfl_sync(0xffffffffu, sf[mt][kt][3], srcB);
            pa[mt][0] = f2tf32((c & 1) ? x1 : x0);
            pa[mt][1] = f2tf32((c & 1) ? z1 : z0);
            pa[mt][2] = f2tf32((c & 1) ? y1 : y0);
            pa[mt][3] = f2tf32((c & 1) ? u1 : u0);
        }
        #pragma unroll
        for (int nt = 0; nt < 4; nt++) {
            const float* vp = sV + (kt * 8 + c) * VSTR + nt * 8 + g;
            uint32_t bf[2];
            bf[0] = f2tf32(vp[0]);
            bf[1] = f2tf32(vp[4 * VSTR]);
            mma_tf32(of[0][nt], pa[0], bf);
            mma_tf32(of[1][nt], pa[1], bf);
        }
    }

    // ---- epilogue: normalize + store ----
    #pragma unroll
    for (int mt = 0; mt < 2; mt++) {
        #pragma unroll
        for (int hf = 0; hf < 2; hf++) {
            int row = w4 * 32 + mt * 16 + g + hf * 8;
            if (row < NTOK) {
                float inv = 1.f / sum[mt][hf];
                float* op = d_attnout + ((size_t)b * NTOK + row) * EMB + h * HDIM;
                #pragma unroll
                for (int nt = 0; nt < 4; nt++) {
                    int col = nt * 8 + c * 2;
                    float v0 = of[mt][nt][hf * 2 + 0] * inv;
                    float v1 = of[mt][nt][hf * 2 + 1] * inv;
                    *(float2*)&op[col] = make_float2(v0, v1);
                }
            }
        }
    }
}

// ---------------------------------------------------------------------------
// Launch
// ---------------------------------------------------------------------------
extern "C" void kernel_launch(void* const* d_in, const int* in_sizes, int n_in,
                              void* d_out, int out_size) {
    const float* x          = (const float*)d_in[0];
    const float* mask       = (const float*)d_in[1];
    const float* qkv_w      = (const float*)d_in[2];
    const float* qkv_b      = (const float*)d_in[3];
    const float* o_w        = (const float*)d_in[4];
    const float* o_b        = (const float*)d_in[5];
    const float* bias_table = (const float*)d_in[6];
    const int*   rel_index  = (const int*)d_in[7];
    float* out = (float*)d_out;

    cudaFuncSetAttribute(gemm_qkv_kernel,
        cudaFuncAttributeMaxDynamicSharedMemorySize, GEMM_SMEM_BYTES);
    cudaFuncSetAttribute(gemm_proj_kernel,
        cudaFuncAttributeMaxDynamicSharedMemorySize, GEMM_SMEM_BYTES);
    cudaFuncSetAttribute(attn_kernel,
        cudaFuncAttributeMaxDynamicSharedMemorySize, ATTN_SMEM_BYTES);

    combine_bias_kernel<<<dim3((NNP + 255) / 256, NHEADS, NWIN), 256>>>(
        bias_table, rel_index, mask);

    // QKV: M = 200704 (784 tiles of 256), Ncols = 576 (9 tiles of 64)
    gemm_qkv_kernel<<<dim3(9, 784), 256, GEMM_SMEM_BYTES>>>(x, qkv_w, qkv_b);

    // Attention: one CTA per (b, h)
    attn_kernel<<<BATCH * NHEADS, 128, ATTN_SMEM_BYTES>>>();

    // Projection: Ncols = 192 (3 tiles of 64)
    gemm_proj_kernel<<<dim3(3, 784), 256, GEMM_SMEM_BYTES>>>(o_w, o_b, out);
}